// round 1
// baseline (speedup 1.0000x reference)
#include <cuda_runtime.h>

#define NN 50000
#define NE 800000
#define NG 256
#define NF 128
#define SCAN_BLK 1024
#define SCAN_NBLK 49   // ceil(50001/1024) coverage: 49*1024 = 50176

// ---------------- device scratch (no allocation allowed) ----------------
__device__ float d_hA[NN * NF];
__device__ float d_hB[NN * NF];
__device__ float d_hT[NN * NF];
__device__ float d_dinv[NN];
__device__ int   d_cnt[NN];
__device__ int   d_off[NN + 1];
__device__ int   d_cursor[NN];
__device__ int   d_csr_src[NE];
__device__ float d_csr_w[NE];
__device__ int   d_partials[64];
__device__ int   d_is64;
__device__ int   d_gstart[NG + 1];
__device__ float d_hcat[NG * 192];
__device__ float d_m1[NG * 256];
__device__ float d_m2[NG * 256];
__device__ float d_p1[NG * 256];
__device__ float d_p2[NG * 256];

// ---------------- int32/int64 index handling ----------------
__device__ __forceinline__ int ldidx(const void* p, long long i) {
    if (d_is64) return (int)((const long long*)p)[i];
    return ((const int*)p)[i];
}

__global__ void k_detect(const void* edge) {
    if (threadIdx.x == 0) {
        // If data is int64 (values < 2^31), every odd int32 word is 0.
        const int* p = (const int*)edge;
        int any = 0;
        for (int i = 0; i < 64; i++) any |= p[2 * i + 1];
        d_is64 = (any == 0) ? 1 : 0;
    }
}

// ---------------- prep kernels ----------------
__global__ void k_init() {
    int i = blockIdx.x * blockDim.x + threadIdx.x;
    if (i < NN) d_cnt[i] = 0;
    if (i <= NG) d_gstart[i] = NN;
}

__global__ void k_hist(const void* edge) {
    int e = blockIdx.x * blockDim.x + threadIdx.x;
    if (e >= NE) return;
    int c = ldidx(edge, (long long)NE + e);
    atomicAdd(&d_cnt[c], 1);
}

__global__ void k_scan1() {
    __shared__ int sm[SCAN_BLK];
    int idx = blockIdx.x * SCAN_BLK + threadIdx.x;
    sm[threadIdx.x] = (idx < NN) ? d_cnt[idx] : 0;
    __syncthreads();
    for (int d = SCAN_BLK / 2; d > 0; d >>= 1) {
        if (threadIdx.x < d) sm[threadIdx.x] += sm[threadIdx.x + d];
        __syncthreads();
    }
    if (threadIdx.x == 0) d_partials[blockIdx.x] = sm[0];
}

__global__ void k_scan2(int nblk) {
    if (threadIdx.x == 0) {
        int run = 0;
        for (int b = 0; b < nblk; b++) {
            int t = d_partials[b];
            d_partials[b] = run;
            run += t;
        }
    }
}

__global__ void k_scan3() {
    __shared__ int sm[2][SCAN_BLK];
    int t = threadIdx.x;
    int idx = blockIdx.x * SCAN_BLK + t;
    int v = (idx < NN) ? d_cnt[idx] : 0;
    sm[0][t] = v;
    __syncthreads();
    int cur = 0;
    for (int d = 1; d < SCAN_BLK; d <<= 1) {
        int add = (t >= d) ? sm[cur][t - d] : 0;
        sm[cur ^ 1][t] = sm[cur][t] + add;
        cur ^= 1;
        __syncthreads();
    }
    int incl = sm[cur][t];
    if (idx <= NN) d_off[idx] = d_partials[blockIdx.x] + incl - v;
}

__global__ void k_dinv_cursor() {
    int i = blockIdx.x * blockDim.x + threadIdx.x;
    if (i >= NN) return;
    d_dinv[i] = rsqrtf((float)d_cnt[i] + 1.0f);
    d_cursor[i] = d_off[i];
}

__global__ void k_fill(const void* edge) {
    int e = blockIdx.x * blockDim.x + threadIdx.x;
    if (e >= NE) return;
    int r = ldidx(edge, e);
    int c = ldidx(edge, (long long)NE + e);
    int p = atomicAdd(&d_cursor[c], 1);
    d_csr_src[p] = r;
    d_csr_w[p] = d_dinv[r] * d_dinv[c];
}

__global__ void k_bounds(const void* batch) {
    int i = blockIdx.x * blockDim.x + threadIdx.x;
    if (i >= NN) return;
    int b = ldidx(batch, i);
    int prev = (i == 0) ? -1 : ldidx(batch, i - 1);
    for (int g = prev + 1; g <= b; g++) d_gstart[g] = i;
}

// ---------------- node GEMM: C[n,j] = sum_k A[n,k]*W[j,k] (+bias) ----------------
// BM=64 rows/block, full 128 cols, BK=16. 256 threads, each computes 8x4.
__global__ __launch_bounds__(256) void k_gemm128(
    const float* __restrict__ A, const float* __restrict__ W,
    const float* __restrict__ bias, float* __restrict__ C, int nrows)
{
    __shared__ float Ast[16][68];    // transposed A tile, padded
    __shared__ float Wst[16][132];   // transposed W tile, padded

    int tid = threadIdx.x;
    int tx = tid & 31;   // cols tx*4 .. tx*4+3
    int ty = tid >> 5;   // rows ty*8 .. ty*8+7
    int row0 = blockIdx.x * 64;

    float acc[8][4];
#pragma unroll
    for (int r = 0; r < 8; r++)
#pragma unroll
        for (int c = 0; c < 4; c++) acc[r][c] = 0.f;

    int lr = tid >> 2;          // A-load row 0..63
    int lc = (tid & 3) * 4;     // 0,4,8,12
    int garow = row0 + lr;

    for (int kk = 0; kk < 128; kk += 16) {
        float4 av = make_float4(0.f, 0.f, 0.f, 0.f);
        if (garow < nrows) av = *(const float4*)(A + (size_t)garow * 128 + kk + lc);
        Ast[lc + 0][lr] = av.x; Ast[lc + 1][lr] = av.y;
        Ast[lc + 2][lr] = av.z; Ast[lc + 3][lr] = av.w;

#pragma unroll
        for (int q = 0; q < 2; q++) {
            int li = tid * 2 + q;       // 0..511
            int j = li >> 2;            // 0..127
            int c4 = (li & 3) * 4;
            float4 wv = *(const float4*)(W + j * 128 + kk + c4);
            Wst[c4 + 0][j] = wv.x; Wst[c4 + 1][j] = wv.y;
            Wst[c4 + 2][j] = wv.z; Wst[c4 + 3][j] = wv.w;
        }
        __syncthreads();

#pragma unroll
        for (int k = 0; k < 16; k++) {
            float4 a0 = *(const float4*)&Ast[k][ty * 8];
            float4 a1 = *(const float4*)&Ast[k][ty * 8 + 4];
            float4 wv = *(const float4*)&Wst[k][tx * 4];
            float ar[8] = {a0.x, a0.y, a0.z, a0.w, a1.x, a1.y, a1.z, a1.w};
            float wr[4] = {wv.x, wv.y, wv.z, wv.w};
#pragma unroll
            for (int r = 0; r < 8; r++)
#pragma unroll
                for (int c = 0; c < 4; c++)
                    acc[r][c] = fmaf(ar[r], wr[c], acc[r][c]);
        }
        __syncthreads();
    }

    float4 bv = make_float4(0.f, 0.f, 0.f, 0.f);
    if (bias) bv = *(const float4*)(bias + tx * 4);
#pragma unroll
    for (int r = 0; r < 8; r++) {
        int grow = row0 + ty * 8 + r;
        if (grow < nrows) {
            float4 o;
            o.x = acc[r][0] + bv.x; o.y = acc[r][1] + bv.y;
            o.z = acc[r][2] + bv.z; o.w = acc[r][3] + bv.w;
            *(float4*)(C + (size_t)grow * 128 + tx * 4) = o;
        }
    }
}

// ---------------- GCN aggregation: warp per node, CSR gather ----------------
__global__ __launch_bounds__(256) void k_agg(const float* __restrict__ ht,
                                             const float* __restrict__ bias,
                                             float* __restrict__ out)
{
    int node = (int)((blockIdx.x * (unsigned)blockDim.x + threadIdx.x) >> 5);
    if (node >= NN) return;
    int lane = threadIdx.x & 31;

    float di = d_dinv[node];
    float sc = di * di;
    float4 h4 = *(const float4*)(ht + (size_t)node * 128 + lane * 4);
    float4 acc;
    acc.x = sc * h4.x; acc.y = sc * h4.y; acc.z = sc * h4.z; acc.w = sc * h4.w;

    int s = d_off[node], e = d_off[node + 1];
    for (int p = s; p < e; p++) {
        int src = __ldg(&d_csr_src[p]);
        float w = __ldg(&d_csr_w[p]);
        float4 v = *(const float4*)(ht + (size_t)src * 128 + lane * 4);
        acc.x = fmaf(w, v.x, acc.x);
        acc.y = fmaf(w, v.y, acc.y);
        acc.z = fmaf(w, v.z, acc.z);
        acc.w = fmaf(w, v.w, acc.w);
    }
    float4 b4 = *(const float4*)(bias + lane * 4);
    acc.x = fmaxf(acc.x + b4.x, 0.f);
    acc.y = fmaxf(acc.y + b4.y, 0.f);
    acc.z = fmaxf(acc.z + b4.z, 0.f);
    acc.w = fmaxf(acc.w + b4.w, 0.f);
    *(float4*)(out + (size_t)node * 128 + lane * 4) = acc;
}

// ---------------- mean pool per graph (deterministic) ----------------
__global__ void k_pool(const float* __restrict__ h, float* __restrict__ hcat) {
    int g = blockIdx.x;
    int s = d_gstart[g], e = d_gstart[g + 1];
    int t = threadIdx.x;           // 256
    int f = t & 127;
    int half = t >> 7;
    float acc = 0.f;
    for (int n = s + half; n < e; n += 2)
        acc += h[(size_t)n * 128 + f];
    __shared__ float sm[256];
    sm[t] = acc;
    __syncthreads();
    if (t < 128) {
        float v = sm[t] + sm[t + 128];
        int cnt = e - s;
        hcat[g * 192 + t] = v / (float)max(cnt, 1);
    }
}

// ---------------- small per-graph GEMM: C[g,j] = act(A[g,:] . W[j,:] + b[j]) ----------------
__global__ void k_small(const float* __restrict__ A, int sA,
                        const float* __restrict__ W, const float* __restrict__ bias,
                        float* __restrict__ C, int sC,
                        int kin, int nout, int do_relu)
{
    __shared__ float As[256];
    int g = blockIdx.x;
    int t = threadIdx.x;
    for (int k = t; k < kin; k += blockDim.x) As[k] = A[g * sA + k];
    __syncthreads();
    for (int j = t; j < nout; j += blockDim.x) {
        const float* wr = W + (size_t)j * kin;
        float a0 = 0.f, a1 = 0.f, a2 = 0.f, a3 = 0.f;
        for (int k = 0; k < kin; k += 4) {
            a0 = fmaf(As[k + 0], wr[k + 0], a0);
            a1 = fmaf(As[k + 1], wr[k + 1], a1);
            a2 = fmaf(As[k + 2], wr[k + 2], a2);
            a3 = fmaf(As[k + 3], wr[k + 3], a3);
        }
        float v = a0 + a1 + a2 + a3 + bias[j];
        if (do_relu) v = fmaxf(v, 0.f);
        C[g * sC + j] = v;
    }
}

// ---------------- host ----------------
extern "C" void kernel_launch(void* const* d_in, const int* in_sizes, int n_in,
                              void* d_out, int out_size)
{
    const float* x    = (const float*)d_in[0];
    const void*  ei   = d_in[1];
    const void*  bi   = d_in[2];
    const float* mol  = (const float*)d_in[3];
    const float* gcnW = (const float*)d_in[4];
    const float* gcnB = (const float*)d_in[5];
    const float* goW  = (const float*)d_in[6];
    const float* goB  = (const float*)d_in[7];
    const float* mW   = (const float*)d_in[8];
    const float* mB   = (const float*)d_in[9];
    const float* moW  = (const float*)d_in[10];
    const float* moB  = (const float*)d_in[11];
    const float* p1W  = (const float*)d_in[12];
    const float* p1B  = (const float*)d_in[13];
    const float* p2W  = (const float*)d_in[14];
    const float* p2B  = (const float*)d_in[15];
    const float* oW   = (const float*)d_in[16];
    const float* oB   = (const float*)d_in[17];
    float* out = (float*)d_out;

    void *pA, *pB, *pT, *pcat, *pm1, *pm2, *pp1, *pp2;
    cudaGetSymbolAddress(&pA, d_hA);
    cudaGetSymbolAddress(&pB, d_hB);
    cudaGetSymbolAddress(&pT, d_hT);
    cudaGetSymbolAddress(&pcat, d_hcat);
    cudaGetSymbolAddress(&pm1, d_m1);
    cudaGetSymbolAddress(&pm2, d_m2);
    cudaGetSymbolAddress(&pp1, d_p1);
    cudaGetSymbolAddress(&pp2, d_p2);
    float* hA = (float*)pA;
    float* hB = (float*)pB;
    float* hT = (float*)pT;
    float* hcat = (float*)pcat;
    float* m1 = (float*)pm1;
    float* m2 = (float*)pm2;
    float* p1 = (float*)pp1;
    float* p2 = (float*)pp2;

    const int nthr = 256;
    int gN = (NN + nthr - 1) / nthr;
    int gE = (NE + nthr - 1) / nthr;
    int gGemm = (NN + 63) / 64;
    int gAgg = (NN * 32 + nthr - 1) / nthr;

    // -------- CSR + norm prep --------
    k_detect<<<1, 32>>>(ei);
    k_init<<<gN, nthr>>>();
    k_hist<<<gE, nthr>>>(ei);
    k_scan1<<<SCAN_NBLK, SCAN_BLK>>>();
    k_scan2<<<1, 32>>>(SCAN_NBLK);
    k_scan3<<<SCAN_NBLK, SCAN_BLK>>>();
    k_dinv_cursor<<<gN, nthr>>>();
    k_fill<<<gE, nthr>>>(ei);
    k_bounds<<<gN, nthr>>>(bi);

    // -------- GCN stack --------
    k_gemm128<<<gGemm, 256>>>(x, gcnW, nullptr, hT, NN);
    k_agg<<<gAgg, 256>>>(hT, gcnB, hA);
    k_gemm128<<<gGemm, 256>>>(hA, gcnW + 128 * 128, nullptr, hT, NN);
    k_agg<<<gAgg, 256>>>(hT, gcnB + 128, hB);
    k_gemm128<<<gGemm, 256>>>(hB, gcnW + 2 * 128 * 128, nullptr, hT, NN);
    k_agg<<<gAgg, 256>>>(hT, gcnB + 256, hA);
    k_gemm128<<<gGemm, 256>>>(hA, goW, goB, hB, NN);   // bias, no relu

    // -------- pool + heads --------
    k_pool<<<NG, 256>>>(hB, hcat);                                      // hcat[:, :128]
    k_small<<<NG, 256>>>(mol, 256, mW, mB, m1, 256, 256, 256, 1);
    k_small<<<NG, 256>>>(m1, 256, mW + 256 * 256, mB + 256, m2, 256, 256, 256, 1);
    k_small<<<NG, 256>>>(m2, 256, moW, moB, hcat + 128, 192, 256, 64, 1); // hcat[:,128:192]
    k_small<<<NG, 256>>>(hcat, 192, p1W, p1B, p1, 256, 192, 256, 1);
    k_small<<<NG, 256>>>(p1, 256, p2W, p2B, p2, 256, 256, 256, 1);
    k_small<<<NG, 256>>>(p2, 256, oW, oB, out, 1, 256, 1, 0);
}

// round 3
// speedup vs baseline: 1.6619x; 1.6619x over previous
#include <cuda_runtime.h>

#define NN 50000
#define NE 800000
#define NG 256
#define NF 128
#define SCAN_BLK 1024
#define SCAN_NBLK 49   // 49*1024 = 50176 >= NN+1

typedef unsigned long long u64;

// ---------------- device scratch (no allocation allowed) ----------------
__device__ float d_hA[NN * NF];
__device__ float d_hB[NN * NF];
__device__ float d_hT[NN * NF];
__device__ float d_dinv[NN];
__device__ int   d_cnt[NN];
__device__ int   d_off[NN + 1];
__device__ int   d_cursor[NN];
__device__ int2  d_csr[NE];          // {src, w as int bits}
__device__ int   d_partials[64];
__device__ int   d_is64;
__device__ int   d_gstart[NG + 1];

// ---------------- f32x2 helpers ----------------
__device__ __forceinline__ u64 fma2(u64 a, u64 b, u64 c) {
    u64 d;
    asm("fma.rn.f32x2 %0, %1, %2, %3;" : "=l"(d) : "l"(a), "l"(b), "l"(c));
    return d;
}
__device__ __forceinline__ u64 dup2(float x) {
    u64 d;
    asm("mov.b64 %0, {%1, %1};" : "=l"(d) : "f"(x));
    return d;
}
__device__ __forceinline__ float lo2(u64 v) {
    float a, b;
    asm("mov.b64 {%0, %1}, %2;" : "=f"(a), "=f"(b) : "l"(v));
    (void)b;
    return a;
}
__device__ __forceinline__ float hi2(u64 v) {
    float a, b;
    asm("mov.b64 {%0, %1}, %2;" : "=f"(a), "=f"(b) : "l"(v));
    (void)a;
    return b;
}

// ---------------- int32/int64 index handling ----------------
__device__ __forceinline__ int ldidx(const void* p, long long i) {
    if (d_is64) return (int)((const long long*)p)[i];
    return ((const int*)p)[i];
}

// ---------------- prep ----------------
__global__ void k_init(const void* edge) {
    int i = blockIdx.x * blockDim.x + threadIdx.x;
    if (i == 0) {
        const int* p = (const int*)edge;
        int any = 0;
        for (int j = 0; j < 64; j++) any |= p[2 * j + 1];
        d_is64 = (any == 0) ? 1 : 0;
    }
    if (i < NN) d_cnt[i] = 0;
    if (i <= NG) d_gstart[i] = NN;
}

__global__ void k_hist(const void* edge) {
    int e = blockIdx.x * blockDim.x + threadIdx.x;
    if (e >= NE) return;
    int c = ldidx(edge, (long long)NE + e);
    atomicAdd(&d_cnt[c], 1);
}

__global__ void k_scan1() {
    __shared__ int sm[SCAN_BLK];
    int idx = blockIdx.x * SCAN_BLK + threadIdx.x;
    sm[threadIdx.x] = (idx < NN) ? d_cnt[idx] : 0;
    __syncthreads();
    for (int d = SCAN_BLK / 2; d > 0; d >>= 1) {
        if (threadIdx.x < d) sm[threadIdx.x] += sm[threadIdx.x + d];
        __syncthreads();
    }
    if (threadIdx.x == 0) d_partials[blockIdx.x] = sm[0];
}

// block-local scan + cross-block base + dinv + cursor, all in one kernel
__global__ void k_scan3() {
    __shared__ int sm[2][SCAN_BLK];
    __shared__ int pb[64];
    int t = threadIdx.x;
    int idx = blockIdx.x * SCAN_BLK + t;
    int v = (idx < NN) ? d_cnt[idx] : 0;
    sm[0][t] = v;
    if (t < 64) pb[t] = (t < (int)blockIdx.x && t < SCAN_NBLK) ? d_partials[t] : 0;
    __syncthreads();
    if (t < 32) pb[t] += pb[t + 32];
    __syncthreads();
    if (t < 16) pb[t] += pb[t + 16];
    __syncthreads();
    if (t < 8) pb[t] += pb[t + 8];
    __syncthreads();
    if (t < 4) { pb[t] += pb[t + 4]; }
    __syncthreads();
    int base = pb[0] + pb[1] + pb[2] + pb[3];
    int cur = 0;
    for (int d = 1; d < SCAN_BLK; d <<= 1) {
        int add = (t >= d) ? sm[cur][t - d] : 0;
        sm[cur ^ 1][t] = sm[cur][t] + add;
        cur ^= 1;
        __syncthreads();
    }
    int excl = base + sm[cur][t] - v;
    if (idx <= NN) d_off[idx] = excl;
    if (idx < NN) {
        d_dinv[idx] = rsqrtf((float)v + 1.0f);
        d_cursor[idx] = excl;
    }
}

__global__ void k_fill(const void* edge) {
    int e = blockIdx.x * blockDim.x + threadIdx.x;
    if (e >= NE) return;
    int r = ldidx(edge, e);
    int c = ldidx(edge, (long long)NE + e);
    int p = atomicAdd(&d_cursor[c], 1);
    d_csr[p] = make_int2(r, __float_as_int(d_dinv[r] * d_dinv[c]));
}

__global__ void k_bounds(const void* batch) {
    int i = blockIdx.x * blockDim.x + threadIdx.x;
    if (i >= NN) return;
    int b = ldidx(batch, i);
    int prev = (i == 0) ? -1 : ldidx(batch, i - 1);
    for (int g = prev + 1; g <= b; g++) d_gstart[g] = i;
}

// ---------------- node GEMM via FFMA2: C[n,j] = sum_k A[n,k]*W[j,k] ----------------
// BM=128, BN=128, BK=16, 256 threads, 8 rows x 8 cols per thread.
__global__ __launch_bounds__(256) void k_gemm2(
    const float* __restrict__ A, const float* __restrict__ W,
    float* __restrict__ C, int nrows)
{
    __shared__ float Ast[16][132];   // [k][row], row-pairs contiguous
    __shared__ float Wst[16][132];   // [k][col]

    int tid = threadIdx.x;
    int tx = tid & 15;    // cols tx*4..+3 and 64+tx*4..+3
    int ty = tid >> 4;    // rows ty*8..+7
    int row0 = blockIdx.x * 128;

    u64 acc[4][8];
#pragma unroll
    for (int r = 0; r < 4; r++)
#pragma unroll
        for (int c = 0; c < 8; c++) acc[r][c] = 0ull;

    int lr = tid >> 1;           // 0..127
    int lc = (tid & 1) * 8;      // 0 or 8
    int garow = row0 + lr;

    for (int kk = 0; kk < 128; kk += 16) {
        float4 av0 = make_float4(0.f, 0.f, 0.f, 0.f);
        float4 av1 = make_float4(0.f, 0.f, 0.f, 0.f);
        if (garow < nrows) {
            av0 = *(const float4*)(A + (size_t)garow * 128 + kk + lc);
            av1 = *(const float4*)(A + (size_t)garow * 128 + kk + lc + 4);
        }
        Ast[lc + 0][lr] = av0.x; Ast[lc + 1][lr] = av0.y;
        Ast[lc + 2][lr] = av0.z; Ast[lc + 3][lr] = av0.w;
        Ast[lc + 4][lr] = av1.x; Ast[lc + 5][lr] = av1.y;
        Ast[lc + 6][lr] = av1.z; Ast[lc + 7][lr] = av1.w;

        float4 wv0 = *(const float4*)(W + (size_t)lr * 128 + kk + lc);
        float4 wv1 = *(const float4*)(W + (size_t)lr * 128 + kk + lc + 4);
        Wst[lc + 0][lr] = wv0.x; Wst[lc + 1][lr] = wv0.y;
        Wst[lc + 2][lr] = wv0.z; Wst[lc + 3][lr] = wv0.w;
        Wst[lc + 4][lr] = wv1.x; Wst[lc + 5][lr] = wv1.y;
        Wst[lc + 6][lr] = wv1.z; Wst[lc + 7][lr] = wv1.w;
        __syncthreads();

#pragma unroll
        for (int k = 0; k < 16; k++) {
            const u64* arow = (const u64*)&Ast[k][ty * 8];
            u64 a0 = arow[0], a1 = arow[1], a2 = arow[2], a3 = arow[3];
            float4 w0 = *(const float4*)&Wst[k][tx * 4];
            float4 w1 = *(const float4*)&Wst[k][64 + tx * 4];
            u64 wd[8];
            wd[0] = dup2(w0.x); wd[1] = dup2(w0.y);
            wd[2] = dup2(w0.z); wd[3] = dup2(w0.w);
            wd[4] = dup2(w1.x); wd[5] = dup2(w1.y);
            wd[6] = dup2(w1.z); wd[7] = dup2(w1.w);
#pragma unroll
            for (int c = 0; c < 8; c++) {
                acc[0][c] = fma2(a0, wd[c], acc[0][c]);
                acc[1][c] = fma2(a1, wd[c], acc[1][c]);
                acc[2][c] = fma2(a2, wd[c], acc[2][c]);
                acc[3][c] = fma2(a3, wd[c], acc[3][c]);
            }
        }
        __syncthreads();
    }

#pragma unroll
    for (int rp = 0; rp < 4; rp++) {
        int re = row0 + ty * 8 + rp * 2;
        int ro = re + 1;
        float4 e0 = make_float4(lo2(acc[rp][0]), lo2(acc[rp][1]), lo2(acc[rp][2]), lo2(acc[rp][3]));
        float4 e1 = make_float4(lo2(acc[rp][4]), lo2(acc[rp][5]), lo2(acc[rp][6]), lo2(acc[rp][7]));
        float4 o0 = make_float4(hi2(acc[rp][0]), hi2(acc[rp][1]), hi2(acc[rp][2]), hi2(acc[rp][3]));
        float4 o1 = make_float4(hi2(acc[rp][4]), hi2(acc[rp][5]), hi2(acc[rp][6]), hi2(acc[rp][7]));
        if (re < nrows) {
            *(float4*)(C + (size_t)re * 128 + tx * 4) = e0;
            *(float4*)(C + (size_t)re * 128 + 64 + tx * 4) = e1;
        }
        if (ro < nrows) {
            *(float4*)(C + (size_t)ro * 128 + tx * 4) = o0;
            *(float4*)(C + (size_t)ro * 128 + 64 + tx * 4) = o1;
        }
    }
}

// ---------------- GCN aggregation: warp per node, 4-way unrolled CSR gather ----------------
__global__ __launch_bounds__(256) void k_agg(const float* __restrict__ ht,
                                             const float* __restrict__ bias,
                                             float* __restrict__ out)
{
    int node = (int)((blockIdx.x * (unsigned)blockDim.x + threadIdx.x) >> 5);
    if (node >= NN) return;
    int lane = threadIdx.x & 31;
    const float4* base = (const float4*)ht;

    float di = d_dinv[node];
    float sc = di * di;
    float4 h4 = __ldg(base + (size_t)node * 32 + lane);
    float4 a0 = make_float4(sc * h4.x, sc * h4.y, sc * h4.z, sc * h4.w);
    float4 a1 = make_float4(0.f, 0.f, 0.f, 0.f);
    float4 a2 = a1, a3 = a1;

    int p = d_off[node], e = d_off[node + 1];
    for (; p + 4 <= e; p += 4) {
        int2 c0 = __ldg(&d_csr[p + 0]);
        int2 c1 = __ldg(&d_csr[p + 1]);
        int2 c2 = __ldg(&d_csr[p + 2]);
        int2 c3 = __ldg(&d_csr[p + 3]);
        float4 v0 = __ldg(base + (size_t)c0.x * 32 + lane);
        float4 v1 = __ldg(base + (size_t)c1.x * 32 + lane);
        float4 v2 = __ldg(base + (size_t)c2.x * 32 + lane);
        float4 v3 = __ldg(base + (size_t)c3.x * 32 + lane);
        float w0 = __int_as_float(c0.y), w1 = __int_as_float(c1.y);
        float w2 = __int_as_float(c2.y), w3 = __int_as_float(c3.y);
        a0.x = fmaf(w0, v0.x, a0.x); a0.y = fmaf(w0, v0.y, a0.y);
        a0.z = fmaf(w0, v0.z, a0.z); a0.w = fmaf(w0, v0.w, a0.w);
        a1.x = fmaf(w1, v1.x, a1.x); a1.y = fmaf(w1, v1.y, a1.y);
        a1.z = fmaf(w1, v1.z, a1.z); a1.w = fmaf(w1, v1.w, a1.w);
        a2.x = fmaf(w2, v2.x, a2.x); a2.y = fmaf(w2, v2.y, a2.y);
        a2.z = fmaf(w2, v2.z, a2.z); a2.w = fmaf(w2, v2.w, a2.w);
        a3.x = fmaf(w3, v3.x, a3.x); a3.y = fmaf(w3, v3.y, a3.y);
        a3.z = fmaf(w3, v3.z, a3.z); a3.w = fmaf(w3, v3.w, a3.w);
    }
    for (; p < e; p++) {
        int2 c = __ldg(&d_csr[p]);
        float4 v = __ldg(base + (size_t)c.x * 32 + lane);
        float w = __int_as_float(c.y);
        a0.x = fmaf(w, v.x, a0.x); a0.y = fmaf(w, v.y, a0.y);
        a0.z = fmaf(w, v.z, a0.z); a0.w = fmaf(w, v.w, a0.w);
    }
    float4 b4 = __ldg((const float4*)bias + lane);
    float4 r;
    r.x = fmaxf(a0.x + a1.x + a2.x + a3.x + b4.x, 0.f);
    r.y = fmaxf(a0.y + a1.y + a2.y + a3.y + b4.y, 0.f);
    r.z = fmaxf(a0.z + a1.z + a2.z + a3.z + b4.z, 0.f);
    r.w = fmaxf(a0.w + a1.w + a2.w + a3.w + b4.w, 0.f);
    *(float4*)(out + (size_t)node * 128 + lane * 4) = r;
}

// ---------------- fused pool + gcn_out + MLP branch + prediction head ----------------
__device__ __forceinline__ float dotN(const float* __restrict__ a,
                                      const float* __restrict__ w, int n) {
    float s0 = 0.f, s1 = 0.f, s2 = 0.f, s3 = 0.f;
    for (int k = 0; k < n; k += 4) {
        float4 wv = __ldg((const float4*)(w + k));
        s0 = fmaf(a[k + 0], wv.x, s0);
        s1 = fmaf(a[k + 1], wv.y, s1);
        s2 = fmaf(a[k + 2], wv.z, s2);
        s3 = fmaf(a[k + 3], wv.w, s3);
    }
    return (s0 + s1) + (s2 + s3);
}

__global__ __launch_bounds__(256) void k_heads(
    const float* __restrict__ mol,
    const float* __restrict__ mW, const float* __restrict__ mB,
    const float* __restrict__ moW, const float* __restrict__ moB,
    const float* __restrict__ hnode,
    const float* __restrict__ goW, const float* __restrict__ goB,
    const float* __restrict__ p1W, const float* __restrict__ p1B,
    const float* __restrict__ p2W, const float* __restrict__ p2B,
    const float* __restrict__ oW, const float* __restrict__ oB,
    float* __restrict__ out)
{
    __shared__ float a[256], b[256], cat[192], pooled[128], red[256];
    int g = blockIdx.x, t = threadIdx.x;

    a[t] = mol[g * 256 + t];
    __syncthreads();
    b[t] = fmaxf(dotN(a, mW + t * 256, 256) + mB[t], 0.f);
    __syncthreads();
    a[t] = fmaxf(dotN(b, mW + 65536 + t * 256, 256) + mB[256 + t], 0.f);
    __syncthreads();
    if (t < 64) cat[128 + t] = fmaxf(dotN(a, moW + t * 256, 256) + moB[t], 0.f);

    // mean pool of GCN node features for this graph
    int s = d_gstart[g], e = d_gstart[g + 1];
    float acc = 0.f;
    int f = t & 127, half = t >> 7;
    for (int n = s + half; n < e; n += 2) acc += hnode[(size_t)n * 128 + f];
    red[t] = acc;
    __syncthreads();
    if (t < 128) pooled[t] = (red[t] + red[t + 128]) / (float)max(e - s, 1);
    __syncthreads();
    // gcn_out applied to pooled features (linear commutes with mean pool)
    if (t < 128) cat[t] = (e > s) ? (dotN(pooled, goW + t * 128, 128) + goB[t]) : 0.f;
    __syncthreads();

    b[t] = fmaxf(dotN(cat, p1W + t * 192, 192) + p1B[t], 0.f);
    __syncthreads();
    a[t] = fmaxf(dotN(b, p2W + t * 256, 256) + p2B[t], 0.f);
    __syncthreads();
    red[t] = a[t] * oW[t];
    __syncthreads();
    for (int d = 128; d > 0; d >>= 1) {
        if (t < d) red[t] += red[t + d];
        __syncthreads();
    }
    if (t == 0) out[g] = red[0] + oB[0];
}

// ---------------- host ----------------
extern "C" void kernel_launch(void* const* d_in, const int* in_sizes, int n_in,
                              void* d_out, int out_size)
{
    const float* x    = (const float*)d_in[0];
    const void*  ei   = d_in[1];
    const void*  bi   = d_in[2];
    const float* mol  = (const float*)d_in[3];
    const float* gcnW = (const float*)d_in[4];
    const float* gcnB = (const float*)d_in[5];
    const float* goW  = (const float*)d_in[6];
    const float* goB  = (const float*)d_in[7];
    const float* mW   = (const float*)d_in[8];
    const float* mB   = (const float*)d_in[9];
    const float* moW  = (const float*)d_in[10];
    const float* moB  = (const float*)d_in[11];
    const float* p1W  = (const float*)d_in[12];
    const float* p1B  = (const float*)d_in[13];
    const float* p2W  = (const float*)d_in[14];
    const float* p2B  = (const float*)d_in[15];
    const float* oW   = (const float*)d_in[16];
    const float* oB   = (const float*)d_in[17];
    float* out = (float*)d_out;

    void *pA, *pB, *pT;
    cudaGetSymbolAddress(&pA, d_hA);
    cudaGetSymbolAddress(&pB, d_hB);
    cudaGetSymbolAddress(&pT, d_hT);
    float* hA = (float*)pA;
    float* hB = (float*)pB;
    float* hT = (float*)pT;

    const int nthr = 256;
    int gN = (NN + nthr - 1) / nthr;
    int gE = (NE + nthr - 1) / nthr;
    int gGemm = (NN + 127) / 128;
    int gAgg = (NN * 32 + nthr - 1) / nthr;

    // -------- CSR + norm prep --------
    k_init<<<gN, nthr>>>(ei);
    k_hist<<<gE, nthr>>>(ei);
    k_scan1<<<SCAN_NBLK, SCAN_BLK>>>();
    k_scan3<<<SCAN_NBLK, SCAN_BLK>>>();
    k_fill<<<gE, nthr>>>(ei);
    k_bounds<<<gN, nthr>>>(bi);

    // -------- GCN stack (gcn_out folded into heads after pooling) --------
    k_gemm2<<<gGemm, 256>>>(x, gcnW, hT, NN);
    k_agg<<<gAgg, 256>>>(hT, gcnB, hA);
    k_gemm2<<<gGemm, 256>>>(hA, gcnW + 128 * 128, hT, NN);
    k_agg<<<gAgg, 256>>>(hT, gcnB + 128, hB);
    k_gemm2<<<gGemm, 256>>>(hB, gcnW + 2 * 128 * 128, hT, NN);
    k_agg<<<gAgg, 256>>>(hT, gcnB + 256, hA);

    // -------- fused pool + heads --------
    k_heads<<<NG, 256>>>(mol, mW, mB, moW, moB, hA, goW, goB,
                         p1W, p1B, p2W, p2B, oW, oB, out);
}

// round 4
// speedup vs baseline: 1.8564x; 1.1170x over previous
#include <cuda_runtime.h>

#define NN 50000
#define NE 800000
#define NG 256
#define NF 128
#define SCAN_BLK 1024
#define SCAN_NBLK 49   // 49*1024 = 50176 >= NN+1

typedef unsigned long long u64;

// ---------------- device scratch (no allocation allowed) ----------------
__device__ float d_hA[NN * NF];
__device__ float d_hB[NN * NF];
__device__ float d_hT[NN * NF];
__device__ float d_dinv[NN];
__device__ int   d_cnt[NN];
__device__ int   d_off[NN + 1];
__device__ int   d_cursor[NN];
__device__ int2  d_csr[NE];          // {src, w as int bits}
__device__ int   d_partials[64];
__device__ int   d_is64;
__device__ int   d_gstart[NG + 1];
__device__ float d_mlpo[NG * 64];

// ---------------- f32x2 helpers ----------------
__device__ __forceinline__ u64 fma2(u64 a, u64 b, u64 c) {
    u64 d;
    asm("fma.rn.f32x2 %0, %1, %2, %3;" : "=l"(d) : "l"(a), "l"(b), "l"(c));
    return d;
}
__device__ __forceinline__ u64 dup2(float x) {
    u64 d;
    asm("mov.b64 %0, {%1, %1};" : "=l"(d) : "f"(x));
    return d;
}
__device__ __forceinline__ float lo2(u64 v) {
    float a, b;
    asm("mov.b64 {%0, %1}, %2;" : "=f"(a), "=f"(b) : "l"(v));
    (void)b;
    return a;
}
__device__ __forceinline__ float hi2(u64 v) {
    float a, b;
    asm("mov.b64 {%0, %1}, %2;" : "=f"(a), "=f"(b) : "l"(v));
    (void)a;
    return b;
}

// ---------------- int32/int64 index handling ----------------
__device__ __forceinline__ int ldidx(const void* p, long long i) {
    if (d_is64) return (int)((const long long*)p)[i];
    return ((const int*)p)[i];
}

// ---------------- prep ----------------
__global__ void k_detect(const void* edge) {
    if (threadIdx.x == 0) {
        const int* p = (const int*)edge;
        int any = 0;
        for (int j = 0; j < 64; j++) any |= p[2 * j + 1];
        d_is64 = (any == 0) ? 1 : 0;
    }
}

__global__ void k_init() {
    int i = blockIdx.x * blockDim.x + threadIdx.x;
    if (i < NN) d_cnt[i] = 0;
}

__global__ void k_hist(const void* edge) {
    int e = blockIdx.x * blockDim.x + threadIdx.x;
    if (e >= NE) return;
    int c = ldidx(edge, (long long)NE + e);
    atomicAdd(&d_cnt[c], 1);
}

__global__ void k_scan1() {
    __shared__ int sm[SCAN_BLK];
    int idx = blockIdx.x * SCAN_BLK + threadIdx.x;
    sm[threadIdx.x] = (idx < NN) ? d_cnt[idx] : 0;
    __syncthreads();
    for (int d = SCAN_BLK / 2; d > 0; d >>= 1) {
        if (threadIdx.x < d) sm[threadIdx.x] += sm[threadIdx.x + d];
        __syncthreads();
    }
    if (threadIdx.x == 0) d_partials[blockIdx.x] = sm[0];
}

// block-local scan + cross-block base + dinv + cursor, all in one kernel
__global__ void k_scan3() {
    __shared__ int sm[2][SCAN_BLK];
    __shared__ int pb[64];
    int t = threadIdx.x;
    int idx = blockIdx.x * SCAN_BLK + t;
    int v = (idx < NN) ? d_cnt[idx] : 0;
    sm[0][t] = v;
    if (t < 64) pb[t] = (t < (int)blockIdx.x && t < SCAN_NBLK) ? d_partials[t] : 0;
    __syncthreads();
    if (t < 32) pb[t] += pb[t + 32];
    __syncthreads();
    if (t < 16) pb[t] += pb[t + 16];
    __syncthreads();
    if (t < 8) pb[t] += pb[t + 8];
    __syncthreads();
    if (t < 4) { pb[t] += pb[t + 4]; }
    __syncthreads();
    int base = pb[0] + pb[1] + pb[2] + pb[3];
    int cur = 0;
    for (int d = 1; d < SCAN_BLK; d <<= 1) {
        int add = (t >= d) ? sm[cur][t - d] : 0;
        sm[cur ^ 1][t] = sm[cur][t] + add;
        cur ^= 1;
        __syncthreads();
    }
    int excl = base + sm[cur][t] - v;
    if (idx <= NN) d_off[idx] = excl;
    if (idx < NN) {
        d_dinv[idx] = rsqrtf((float)v + 1.0f);
        d_cursor[idx] = excl;
    }
}

__global__ void k_fill(const void* edge) {
    int e = blockIdx.x * blockDim.x + threadIdx.x;
    if (e >= NE) return;
    int r = ldidx(edge, e);
    int c = ldidx(edge, (long long)NE + e);
    int p = atomicAdd(&d_cursor[c], 1);
    d_csr[p] = make_int2(r, __float_as_int(d_dinv[r] * d_dinv[c]));
}

__global__ void k_bounds(const void* batch) {
    int i = blockIdx.x * blockDim.x + threadIdx.x;
    if (i >= NN) return;
    int b = ldidx(batch, i);
    int prev = (i == 0) ? -1 : ldidx(batch, i - 1);
    for (int g = prev + 1; g <= b; g++) d_gstart[g] = i;
    if (i == NN - 1) {
        for (int g = b + 1; g <= NG; g++) d_gstart[g] = NN;
    }
}

// ---------------- node GEMM via FFMA2: C[n,j] = sum_k A[n,k]*W[j,k] ----------------
// BM=128, BN=128, BK=16, 256 threads, 8 rows x 8 cols per thread.
// Register double-buffered global->smem staging.
__global__ __launch_bounds__(256) void k_gemm2(
    const float* __restrict__ A, const float* __restrict__ W,
    float* __restrict__ C, int nrows)
{
    __shared__ float Ast[16][132];   // [k][row]
    __shared__ float Wst[16][132];   // [k][col]

    int tid = threadIdx.x;
    int tx = tid & 15;    // cols tx*4..+3 and 64+tx*4..+3
    int ty = tid >> 4;    // rows ty*8..+7
    int row0 = blockIdx.x * 128;

    u64 acc[4][8];
#pragma unroll
    for (int r = 0; r < 4; r++)
#pragma unroll
        for (int c = 0; c < 8; c++) acc[r][c] = 0ull;

    int lr = tid >> 1;           // 0..127
    int lc = (tid & 1) * 8;      // 0 or 8
    int garow = row0 + lr;
    bool arow_ok = (garow < nrows);

    float4 av0, av1, wv0, wv1;
    // preload kk = 0
    av0 = av1 = make_float4(0.f, 0.f, 0.f, 0.f);
    if (arow_ok) {
        av0 = *(const float4*)(A + (size_t)garow * 128 + lc);
        av1 = *(const float4*)(A + (size_t)garow * 128 + lc + 4);
    }
    wv0 = *(const float4*)(W + (size_t)lr * 128 + lc);
    wv1 = *(const float4*)(W + (size_t)lr * 128 + lc + 4);

    for (int kk = 0; kk < 128; kk += 16) {
        Ast[lc + 0][lr] = av0.x; Ast[lc + 1][lr] = av0.y;
        Ast[lc + 2][lr] = av0.z; Ast[lc + 3][lr] = av0.w;
        Ast[lc + 4][lr] = av1.x; Ast[lc + 5][lr] = av1.y;
        Ast[lc + 6][lr] = av1.z; Ast[lc + 7][lr] = av1.w;
        Wst[lc + 0][lr] = wv0.x; Wst[lc + 1][lr] = wv0.y;
        Wst[lc + 2][lr] = wv0.z; Wst[lc + 3][lr] = wv0.w;
        Wst[lc + 4][lr] = wv1.x; Wst[lc + 5][lr] = wv1.y;
        Wst[lc + 6][lr] = wv1.z; Wst[lc + 7][lr] = wv1.w;
        __syncthreads();

        if (kk + 16 < 128) {  // stage next tile while computing
            int kn = kk + 16;
            av0 = av1 = make_float4(0.f, 0.f, 0.f, 0.f);
            if (arow_ok) {
                av0 = *(const float4*)(A + (size_t)garow * 128 + kn + lc);
                av1 = *(const float4*)(A + (size_t)garow * 128 + kn + lc + 4);
            }
            wv0 = *(const float4*)(W + (size_t)lr * 128 + kn + lc);
            wv1 = *(const float4*)(W + (size_t)lr * 128 + kn + lc + 4);
        }

#pragma unroll
        for (int k = 0; k < 16; k++) {
            const u64* arow = (const u64*)&Ast[k][ty * 8];
            u64 a0 = arow[0], a1 = arow[1], a2 = arow[2], a3 = arow[3];
            float4 w0 = *(const float4*)&Wst[k][tx * 4];
            float4 w1 = *(const float4*)&Wst[k][64 + tx * 4];
            u64 wd[8];
            wd[0] = dup2(w0.x); wd[1] = dup2(w0.y);
            wd[2] = dup2(w0.z); wd[3] = dup2(w0.w);
            wd[4] = dup2(w1.x); wd[5] = dup2(w1.y);
            wd[6] = dup2(w1.z); wd[7] = dup2(w1.w);
#pragma unroll
            for (int c = 0; c < 8; c++) {
                acc[0][c] = fma2(a0, wd[c], acc[0][c]);
                acc[1][c] = fma2(a1, wd[c], acc[1][c]);
                acc[2][c] = fma2(a2, wd[c], acc[2][c]);
                acc[3][c] = fma2(a3, wd[c], acc[3][c]);
            }
        }
        __syncthreads();
    }

#pragma unroll
    for (int rp = 0; rp < 4; rp++) {
        int re = row0 + ty * 8 + rp * 2;
        int ro = re + 1;
        float4 e0 = make_float4(lo2(acc[rp][0]), lo2(acc[rp][1]), lo2(acc[rp][2]), lo2(acc[rp][3]));
        float4 e1 = make_float4(lo2(acc[rp][4]), lo2(acc[rp][5]), lo2(acc[rp][6]), lo2(acc[rp][7]));
        float4 o0 = make_float4(hi2(acc[rp][0]), hi2(acc[rp][1]), hi2(acc[rp][2]), hi2(acc[rp][3]));
        float4 o1 = make_float4(hi2(acc[rp][4]), hi2(acc[rp][5]), hi2(acc[rp][6]), hi2(acc[rp][7]));
        if (re < nrows) {
            *(float4*)(C + (size_t)re * 128 + tx * 4) = e0;
            *(float4*)(C + (size_t)re * 128 + 64 + tx * 4) = e1;
        }
        if (ro < nrows) {
            *(float4*)(C + (size_t)ro * 128 + tx * 4) = o0;
            *(float4*)(C + (size_t)ro * 128 + 64 + tx * 4) = o1;
        }
    }
}

// ---------------- GCN aggregation: warp per node, 4-way unrolled CSR gather ----------------
__global__ __launch_bounds__(256) void k_agg(const float* __restrict__ ht,
                                             const float* __restrict__ bias,
                                             float* __restrict__ out)
{
    int node = (int)((blockIdx.x * (unsigned)blockDim.x + threadIdx.x) >> 5);
    if (node >= NN) return;
    int lane = threadIdx.x & 31;
    const float4* base = (const float4*)ht;

    float di = d_dinv[node];
    float sc = di * di;
    float4 h4 = __ldg(base + (size_t)node * 32 + lane);
    float4 a0 = make_float4(sc * h4.x, sc * h4.y, sc * h4.z, sc * h4.w);
    float4 a1 = make_float4(0.f, 0.f, 0.f, 0.f);
    float4 a2 = a1, a3 = a1;

    int p = d_off[node], e = d_off[node + 1];
    for (; p + 4 <= e; p += 4) {
        int2 c0 = __ldg(&d_csr[p + 0]);
        int2 c1 = __ldg(&d_csr[p + 1]);
        int2 c2 = __ldg(&d_csr[p + 2]);
        int2 c3 = __ldg(&d_csr[p + 3]);
        float4 v0 = __ldg(base + (size_t)c0.x * 32 + lane);
        float4 v1 = __ldg(base + (size_t)c1.x * 32 + lane);
        float4 v2 = __ldg(base + (size_t)c2.x * 32 + lane);
        float4 v3 = __ldg(base + (size_t)c3.x * 32 + lane);
        float w0 = __int_as_float(c0.y), w1 = __int_as_float(c1.y);
        float w2 = __int_as_float(c2.y), w3 = __int_as_float(c3.y);
        a0.x = fmaf(w0, v0.x, a0.x); a0.y = fmaf(w0, v0.y, a0.y);
        a0.z = fmaf(w0, v0.z, a0.z); a0.w = fmaf(w0, v0.w, a0.w);
        a1.x = fmaf(w1, v1.x, a1.x); a1.y = fmaf(w1, v1.y, a1.y);
        a1.z = fmaf(w1, v1.z, a1.z); a1.w = fmaf(w1, v1.w, a1.w);
        a2.x = fmaf(w2, v2.x, a2.x); a2.y = fmaf(w2, v2.y, a2.y);
        a2.z = fmaf(w2, v2.z, a2.z); a2.w = fmaf(w2, v2.w, a2.w);
        a3.x = fmaf(w3, v3.x, a3.x); a3.y = fmaf(w3, v3.y, a3.y);
        a3.z = fmaf(w3, v3.z, a3.z); a3.w = fmaf(w3, v3.w, a3.w);
    }
    for (; p < e; p++) {
        int2 c = __ldg(&d_csr[p]);
        float4 v = __ldg(base + (size_t)c.x * 32 + lane);
        float w = __int_as_float(c.y);
        a0.x = fmaf(w, v.x, a0.x); a0.y = fmaf(w, v.y, a0.y);
        a0.z = fmaf(w, v.z, a0.z); a0.w = fmaf(w, v.w, a0.w);
    }
    float4 b4 = __ldg((const float4*)bias + lane);
    float4 r;
    r.x = fmaxf(a0.x + a1.x + a2.x + a3.x + b4.x, 0.f);
    r.y = fmaxf(a0.y + a1.y + a2.y + a3.y + b4.y, 0.f);
    r.z = fmaxf(a0.z + a1.z + a2.z + a3.z + b4.z, 0.f);
    r.w = fmaxf(a0.w + a1.w + a2.w + a3.w + b4.w, 0.f);
    *(float4*)(out + (size_t)node * 128 + lane * 4) = r;
}

// ---------------- small dense helpers ----------------
__device__ __forceinline__ float dotN(const float* __restrict__ a,
                                      const float* __restrict__ w, int n) {
    float s0 = 0.f, s1 = 0.f, s2 = 0.f, s3 = 0.f;
    for (int k = 0; k < n; k += 4) {
        float4 wv = __ldg((const float4*)(w + k));
        s0 = fmaf(a[k + 0], wv.x, s0);
        s1 = fmaf(a[k + 1], wv.y, s1);
        s2 = fmaf(a[k + 2], wv.z, s2);
        s3 = fmaf(a[k + 3], wv.w, s3);
    }
    return (s0 + s1) + (s2 + s3);
}

// MLP branch only (independent of the GCN stack) -> d_mlpo[G,64]
__global__ __launch_bounds__(256) void k_mlp(
    const float* __restrict__ mol,
    const float* __restrict__ mW, const float* __restrict__ mB,
    const float* __restrict__ moW, const float* __restrict__ moB)
{
    __shared__ float a[256], b[256];
    int g = blockIdx.x, t = threadIdx.x;
    a[t] = mol[g * 256 + t];
    __syncthreads();
    b[t] = fmaxf(dotN(a, mW + t * 256, 256) + mB[t], 0.f);
    __syncthreads();
    a[t] = fmaxf(dotN(b, mW + 65536 + t * 256, 256) + mB[256 + t], 0.f);
    __syncthreads();
    if (t < 64) d_mlpo[g * 64 + t] = fmaxf(dotN(a, moW + t * 256, 256) + moB[t], 0.f);
}

// pool + gcn_out (folded past the mean-pool) + prediction head
__global__ __launch_bounds__(256) void k_heads2(
    const float* __restrict__ hnode,
    const float* __restrict__ goW, const float* __restrict__ goB,
    const float* __restrict__ p1W, const float* __restrict__ p1B,
    const float* __restrict__ p2W, const float* __restrict__ p2B,
    const float* __restrict__ oW, const float* __restrict__ oB,
    float* __restrict__ out)
{
    __shared__ float cat[192], pooled[128], red[256], b[256], a[256];
    int g = blockIdx.x, t = threadIdx.x;

    int s = d_gstart[g], e = d_gstart[g + 1];
    float acc = 0.f;
    int f = t & 127, half = t >> 7;
    for (int n = s + half; n < e; n += 2) acc += hnode[(size_t)n * 128 + f];
    red[t] = acc;
    if (t < 64) cat[128 + t] = d_mlpo[g * 64 + t];
    __syncthreads();
    if (t < 128) pooled[t] = (red[t] + red[t + 128]) / (float)max(e - s, 1);
    __syncthreads();
    if (t < 128) cat[t] = (e > s) ? (dotN(pooled, goW + t * 128, 128) + goB[t]) : 0.f;
    __syncthreads();

    b[t] = fmaxf(dotN(cat, p1W + t * 192, 192) + p1B[t], 0.f);
    __syncthreads();
    a[t] = fmaxf(dotN(b, p2W + t * 256, 256) + p2B[t], 0.f);
    __syncthreads();
    red[t] = a[t] * oW[t];
    __syncthreads();
    for (int d = 128; d > 0; d >>= 1) {
        if (t < d) red[t] += red[t + d];
        __syncthreads();
    }
    if (t == 0) out[g] = red[0] + oB[0];
}

// ---------------- host ----------------
struct HxCtx {
    cudaStream_t s1, s2;
    cudaEvent_t ev0, ev1, ev2;
    HxCtx() {
        cudaStreamCreateWithFlags(&s1, cudaStreamNonBlocking);
        cudaStreamCreateWithFlags(&s2, cudaStreamNonBlocking);
        cudaEventCreateWithFlags(&ev0, cudaEventDisableTiming);
        cudaEventCreateWithFlags(&ev1, cudaEventDisableTiming);
        cudaEventCreateWithFlags(&ev2, cudaEventDisableTiming);
    }
};

extern "C" void kernel_launch(void* const* d_in, const int* in_sizes, int n_in,
                              void* d_out, int out_size)
{
    static HxCtx ctx;   // streams/events created once (first call is the
                        // non-captured correctness run); same launch DAG
                        // is emitted on every call.

    const float* x    = (const float*)d_in[0];
    const void*  ei   = d_in[1];
    const void*  bi   = d_in[2];
    const float* mol  = (const float*)d_in[3];
    const float* gcnW = (const float*)d_in[4];
    const float* gcnB = (const float*)d_in[5];
    const float* goW  = (const float*)d_in[6];
    const float* goB  = (const float*)d_in[7];
    const float* mW   = (const float*)d_in[8];
    const float* mB   = (const float*)d_in[9];
    const float* moW  = (const float*)d_in[10];
    const float* moB  = (const float*)d_in[11];
    const float* p1W  = (const float*)d_in[12];
    const float* p1B  = (const float*)d_in[13];
    const float* p2W  = (const float*)d_in[14];
    const float* p2B  = (const float*)d_in[15];
    const float* oW   = (const float*)d_in[16];
    const float* oB   = (const float*)d_in[17];
    float* out = (float*)d_out;

    void *pA, *pB, *pT;
    cudaGetSymbolAddress(&pA, d_hA);
    cudaGetSymbolAddress(&pB, d_hB);
    cudaGetSymbolAddress(&pT, d_hT);
    float* hA = (float*)pA;
    float* hB = (float*)pB;
    float* hT = (float*)pT;

    const int nthr = 256;
    int gN = (NN + nthr - 1) / nthr;
    int gE = (NE + nthr - 1) / nthr;
    int gGemm = (NN + 127) / 128;
    int gAgg = (NN * 32 + nthr - 1) / nthr;

    cudaStream_t L = 0;

    // fork point: is64 detection must precede both branches
    k_detect<<<1, 32, 0, L>>>(ei);
    cudaEventRecord(ctx.ev0, L);
    cudaStreamWaitEvent(ctx.s1, ctx.ev0, 0);
    cudaStreamWaitEvent(ctx.s2, ctx.ev0, 0);

    // s1: CSR + norm prep (concurrent with GEMM1 on legacy stream)
    k_init<<<gN, nthr, 0, ctx.s1>>>();
    k_hist<<<gE, nthr, 0, ctx.s1>>>(ei);
    k_scan1<<<SCAN_NBLK, SCAN_BLK, 0, ctx.s1>>>();
    k_scan3<<<SCAN_NBLK, SCAN_BLK, 0, ctx.s1>>>();
    k_fill<<<gE, nthr, 0, ctx.s1>>>(ei);
    cudaEventRecord(ctx.ev1, ctx.s1);

    // s2: graph bounds + MLP branch (independent of GCN stack)
    k_bounds<<<gN, nthr, 0, ctx.s2>>>(bi);
    k_mlp<<<NG, nthr, 0, ctx.s2>>>(mol, mW, mB, moW, moB);
    cudaEventRecord(ctx.ev2, ctx.s2);

    // legacy: GCN stack
    k_gemm2<<<gGemm, 256, 0, L>>>(x, gcnW, hT, NN);
    cudaStreamWaitEvent(L, ctx.ev1, 0);            // join CSR prep
    k_agg<<<gAgg, 256, 0, L>>>(hT, gcnB, hA);
    k_gemm2<<<gGemm, 256, 0, L>>>(hA, gcnW + 128 * 128, hT, NN);
    k_agg<<<gAgg, 256, 0, L>>>(hT, gcnB + 128, hB);
    k_gemm2<<<gGemm, 256, 0, L>>>(hB, gcnW + 2 * 128 * 128, hT, NN);
    k_agg<<<gAgg, 256, 0, L>>>(hT, gcnB + 256, hA);

    // join s2 and finish heads
    cudaStreamWaitEvent(L, ctx.ev2, 0);
    k_heads2<<<NG, 256, 0, L>>>(hA, goW, goB, p1W, p1B, p2W, p2B, oW, oB, out);
}

// round 5
// speedup vs baseline: 1.9125x; 1.0302x over previous
#include <cuda_runtime.h>
#include <cuda_fp16.h>

#define NN 50000
#define NE 800000
#define NG 256
#define NF 128
#define SCAN_BLK 1024
#define SCAN_NBLK 49   // 49*1024 = 50176 >= NN+1

typedef unsigned long long u64;

// ---------------- device scratch (no allocation allowed) ----------------
__device__ float  d_hA[NN * NF];
__device__ float  d_hB[NN * NF];
__device__ __half d_hT[NN * NF];     // fp16 gather buffer
__device__ float  d_dinv[NN];
__device__ int    d_cnt[NN];
__device__ int    d_off[NN + 1];
__device__ int    d_cursor[NN];
__device__ int2   d_csr[NE];         // {src, w as int bits}
__device__ int    d_partials[64];
__device__ int    d_is64;
__device__ int    d_gstart[NG + 1];
__device__ float  d_mlpo[NG * 64];

// ---------------- f32x2 helpers ----------------
__device__ __forceinline__ u64 fma2(u64 a, u64 b, u64 c) {
    u64 d;
    asm("fma.rn.f32x2 %0, %1, %2, %3;" : "=l"(d) : "l"(a), "l"(b), "l"(c));
    return d;
}
__device__ __forceinline__ u64 dup2(float x) {
    u64 d;
    asm("mov.b64 %0, {%1, %1};" : "=l"(d) : "f"(x));
    return d;
}
__device__ __forceinline__ float lo2(u64 v) {
    float a, b;
    asm("mov.b64 {%0, %1}, %2;" : "=f"(a), "=f"(b) : "l"(v));
    (void)b;
    return a;
}
__device__ __forceinline__ float hi2(u64 v) {
    float a, b;
    asm("mov.b64 {%0, %1}, %2;" : "=f"(a), "=f"(b) : "l"(v));
    (void)a;
    return b;
}
__device__ __forceinline__ uint2 pack4h(float4 v) {
    __half2 a = __floats2half2_rn(v.x, v.y);
    __half2 b = __floats2half2_rn(v.z, v.w);
    uint2 r;
    r.x = *(unsigned*)&a;
    r.y = *(unsigned*)&b;
    return r;
}
__device__ __forceinline__ float4 unpack4h(uint2 u) {
    __half2 a = *(__half2*)&u.x;
    __half2 b = *(__half2*)&u.y;
    float2 f0 = __half22float2(a);
    float2 f1 = __half22float2(b);
    return make_float4(f0.x, f0.y, f1.x, f1.y);
}

// ---------------- int32/int64 index handling ----------------
__device__ __forceinline__ int ldidx(const void* p, long long i) {
    if (d_is64) return (int)((const long long*)p)[i];
    return ((const int*)p)[i];
}

// ---------------- prep ----------------
__global__ void k_detect(const void* edge) {
    if (threadIdx.x == 0) {
        const int* p = (const int*)edge;
        int any = 0;
        for (int j = 0; j < 64; j++) any |= p[2 * j + 1];
        d_is64 = (any == 0) ? 1 : 0;
    }
}

__global__ void k_init() {
    int i = blockIdx.x * blockDim.x + threadIdx.x;
    if (i < NN) d_cnt[i] = 0;
}

__global__ void k_hist(const void* edge) {
    int e = blockIdx.x * blockDim.x + threadIdx.x;
    if (e >= NE) return;
    int c = ldidx(edge, (long long)NE + e);
    atomicAdd(&d_cnt[c], 1);
}

__global__ void k_scan1() {
    __shared__ int sm[SCAN_BLK];
    int idx = blockIdx.x * SCAN_BLK + threadIdx.x;
    sm[threadIdx.x] = (idx < NN) ? d_cnt[idx] : 0;
    __syncthreads();
    for (int d = SCAN_BLK / 2; d > 0; d >>= 1) {
        if (threadIdx.x < d) sm[threadIdx.x] += sm[threadIdx.x + d];
        __syncthreads();
    }
    if (threadIdx.x == 0) d_partials[blockIdx.x] = sm[0];
}

__global__ void k_scan3() {
    __shared__ int sm[2][SCAN_BLK];
    __shared__ int pb[64];
    int t = threadIdx.x;
    int idx = blockIdx.x * SCAN_BLK + t;
    int v = (idx < NN) ? d_cnt[idx] : 0;
    sm[0][t] = v;
    if (t < 64) pb[t] = (t < (int)blockIdx.x && t < SCAN_NBLK) ? d_partials[t] : 0;
    __syncthreads();
    if (t < 32) pb[t] += pb[t + 32];
    __syncthreads();
    if (t < 16) pb[t] += pb[t + 16];
    __syncthreads();
    if (t < 8) pb[t] += pb[t + 8];
    __syncthreads();
    if (t < 4) { pb[t] += pb[t + 4]; }
    __syncthreads();
    int base = pb[0] + pb[1] + pb[2] + pb[3];
    int cur = 0;
    for (int d = 1; d < SCAN_BLK; d <<= 1) {
        int add = (t >= d) ? sm[cur][t - d] : 0;
        sm[cur ^ 1][t] = sm[cur][t] + add;
        cur ^= 1;
        __syncthreads();
    }
    int excl = base + sm[cur][t] - v;
    if (idx <= NN) d_off[idx] = excl;
    if (idx < NN) {
        d_dinv[idx] = rsqrtf((float)v + 1.0f);
        d_cursor[idx] = excl;
    }
}

__global__ void k_fill(const void* edge) {
    int e = blockIdx.x * blockDim.x + threadIdx.x;
    if (e >= NE) return;
    int r = ldidx(edge, e);
    int c = ldidx(edge, (long long)NE + e);
    int p = atomicAdd(&d_cursor[c], 1);
    d_csr[p] = make_int2(r, __float_as_int(d_dinv[r] * d_dinv[c]));
}

__global__ void k_bounds(const void* batch) {
    int i = blockIdx.x * blockDim.x + threadIdx.x;
    if (i >= NN) return;
    int b = ldidx(batch, i);
    int prev = (i == 0) ? -1 : ldidx(batch, i - 1);
    for (int g = prev + 1; g <= b; g++) d_gstart[g] = i;
    if (i == NN - 1) {
        for (int g = b + 1; g <= NG; g++) d_gstart[g] = NN;
    }
}

// ---------------- node GEMM via FFMA2, fp16 output ----------------
// BM=128, BN=128, BK=16, 256 threads, 8 rows x 8 cols per thread.
__global__ __launch_bounds__(256) void k_gemm2h(
    const float* __restrict__ A, const float* __restrict__ W,
    __half* __restrict__ C, int nrows)
{
    __shared__ float Ast[16][132];   // [k][row]
    __shared__ float Wst[16][132];   // [k][col]

    int tid = threadIdx.x;
    int tx = tid & 15;
    int ty = tid >> 4;
    int row0 = blockIdx.x * 128;

    u64 acc[4][8];
#pragma unroll
    for (int r = 0; r < 4; r++)
#pragma unroll
        for (int c = 0; c < 8; c++) acc[r][c] = 0ull;

    int lr = tid >> 1;
    int lc = (tid & 1) * 8;
    int garow = row0 + lr;
    bool arow_ok = (garow < nrows);

    float4 av0, av1, wv0, wv1;
    av0 = av1 = make_float4(0.f, 0.f, 0.f, 0.f);
    if (arow_ok) {
        av0 = *(const float4*)(A + (size_t)garow * 128 + lc);
        av1 = *(const float4*)(A + (size_t)garow * 128 + lc + 4);
    }
    wv0 = *(const float4*)(W + (size_t)lr * 128 + lc);
    wv1 = *(const float4*)(W + (size_t)lr * 128 + lc + 4);

    for (int kk = 0; kk < 128; kk += 16) {
        Ast[lc + 0][lr] = av0.x; Ast[lc + 1][lr] = av0.y;
        Ast[lc + 2][lr] = av0.z; Ast[lc + 3][lr] = av0.w;
        Ast[lc + 4][lr] = av1.x; Ast[lc + 5][lr] = av1.y;
        Ast[lc + 6][lr] = av1.z; Ast[lc + 7][lr] = av1.w;
        Wst[lc + 0][lr] = wv0.x; Wst[lc + 1][lr] = wv0.y;
        Wst[lc + 2][lr] = wv0.z; Wst[lc + 3][lr] = wv0.w;
        Wst[lc + 4][lr] = wv1.x; Wst[lc + 5][lr] = wv1.y;
        Wst[lc + 6][lr] = wv1.z; Wst[lc + 7][lr] = wv1.w;
        __syncthreads();

        if (kk + 16 < 128) {
            int kn = kk + 16;
            av0 = av1 = make_float4(0.f, 0.f, 0.f, 0.f);
            if (arow_ok) {
                av0 = *(const float4*)(A + (size_t)garow * 128 + kn + lc);
                av1 = *(const float4*)(A + (size_t)garow * 128 + kn + lc + 4);
            }
            wv0 = *(const float4*)(W + (size_t)lr * 128 + kn + lc);
            wv1 = *(const float4*)(W + (size_t)lr * 128 + kn + lc + 4);
        }

#pragma unroll
        for (int k = 0; k < 16; k++) {
            const u64* arow = (const u64*)&Ast[k][ty * 8];
            u64 a0 = arow[0], a1 = arow[1], a2 = arow[2], a3 = arow[3];
            float4 w0 = *(const float4*)&Wst[k][tx * 4];
            float4 w1 = *(const float4*)&Wst[k][64 + tx * 4];
            u64 wd[8];
            wd[0] = dup2(w0.x); wd[1] = dup2(w0.y);
            wd[2] = dup2(w0.z); wd[3] = dup2(w0.w);
            wd[4] = dup2(w1.x); wd[5] = dup2(w1.y);
            wd[6] = dup2(w1.z); wd[7] = dup2(w1.w);
#pragma unroll
            for (int c = 0; c < 8; c++) {
                acc[0][c] = fma2(a0, wd[c], acc[0][c]);
                acc[1][c] = fma2(a1, wd[c], acc[1][c]);
                acc[2][c] = fma2(a2, wd[c], acc[2][c]);
                acc[3][c] = fma2(a3, wd[c], acc[3][c]);
            }
        }
        __syncthreads();
    }

#pragma unroll
    for (int rp = 0; rp < 4; rp++) {
        int re = row0 + ty * 8 + rp * 2;
        int ro = re + 1;
        float4 e0 = make_float4(lo2(acc[rp][0]), lo2(acc[rp][1]), lo2(acc[rp][2]), lo2(acc[rp][3]));
        float4 e1 = make_float4(lo2(acc[rp][4]), lo2(acc[rp][5]), lo2(acc[rp][6]), lo2(acc[rp][7]));
        float4 o0 = make_float4(hi2(acc[rp][0]), hi2(acc[rp][1]), hi2(acc[rp][2]), hi2(acc[rp][3]));
        float4 o1 = make_float4(hi2(acc[rp][4]), hi2(acc[rp][5]), hi2(acc[rp][6]), hi2(acc[rp][7]));
        if (re < nrows) {
            *(uint2*)(C + (size_t)re * 128 + tx * 4) = pack4h(e0);
            *(uint2*)(C + (size_t)re * 128 + 64 + tx * 4) = pack4h(e1);
        }
        if (ro < nrows) {
            *(uint2*)(C + (size_t)ro * 128 + tx * 4) = pack4h(o0);
            *(uint2*)(C + (size_t)ro * 128 + 64 + tx * 4) = pack4h(o1);
        }
    }
}

// ---------------- GCN aggregation: warp per node, fp16 gather, fp32 accum ----------------
__global__ __launch_bounds__(256) void k_agg(const __half* __restrict__ ht,
                                             const float* __restrict__ bias,
                                             float* __restrict__ out)
{
    int node = (int)((blockIdx.x * (unsigned)blockDim.x + threadIdx.x) >> 5);
    if (node >= NN) return;
    int lane = threadIdx.x & 31;
    const uint2* base = (const uint2*)ht;   // 32 uint2 per 128-half row

    float di = d_dinv[node];
    float sc = di * di;
    float4 h4 = unpack4h(__ldg(base + (size_t)node * 32 + lane));
    float4 a0 = make_float4(sc * h4.x, sc * h4.y, sc * h4.z, sc * h4.w);
    float4 a1 = make_float4(0.f, 0.f, 0.f, 0.f);
    float4 a2 = a1, a3 = a1;

    int p = d_off[node], e = d_off[node + 1];
    for (; p + 4 <= e; p += 4) {
        int2 c0 = __ldg(&d_csr[p + 0]);
        int2 c1 = __ldg(&d_csr[p + 1]);
        int2 c2 = __ldg(&d_csr[p + 2]);
        int2 c3 = __ldg(&d_csr[p + 3]);
        float4 v0 = unpack4h(__ldg(base + (size_t)c0.x * 32 + lane));
        float4 v1 = unpack4h(__ldg(base + (size_t)c1.x * 32 + lane));
        float4 v2 = unpack4h(__ldg(base + (size_t)c2.x * 32 + lane));
        float4 v3 = unpack4h(__ldg(base + (size_t)c3.x * 32 + lane));
        float w0 = __int_as_float(c0.y), w1 = __int_as_float(c1.y);
        float w2 = __int_as_float(c2.y), w3 = __int_as_float(c3.y);
        a0.x = fmaf(w0, v0.x, a0.x); a0.y = fmaf(w0, v0.y, a0.y);
        a0.z = fmaf(w0, v0.z, a0.z); a0.w = fmaf(w0, v0.w, a0.w);
        a1.x = fmaf(w1, v1.x, a1.x); a1.y = fmaf(w1, v1.y, a1.y);
        a1.z = fmaf(w1, v1.z, a1.z); a1.w = fmaf(w1, v1.w, a1.w);
        a2.x = fmaf(w2, v2.x, a2.x); a2.y = fmaf(w2, v2.y, a2.y);
        a2.z = fmaf(w2, v2.z, a2.z); a2.w = fmaf(w2, v2.w, a2.w);
        a3.x = fmaf(w3, v3.x, a3.x); a3.y = fmaf(w3, v3.y, a3.y);
        a3.z = fmaf(w3, v3.z, a3.z); a3.w = fmaf(w3, v3.w, a3.w);
    }
    for (; p < e; p++) {
        int2 c = __ldg(&d_csr[p]);
        float4 v = unpack4h(__ldg(base + (size_t)c.x * 32 + lane));
        float w = __int_as_float(c.y);
        a0.x = fmaf(w, v.x, a0.x); a0.y = fmaf(w, v.y, a0.y);
        a0.z = fmaf(w, v.z, a0.z); a0.w = fmaf(w, v.w, a0.w);
    }
    float4 b4 = __ldg((const float4*)bias + lane);
    float4 r;
    r.x = fmaxf(a0.x + a1.x + a2.x + a3.x + b4.x, 0.f);
    r.y = fmaxf(a0.y + a1.y + a2.y + a3.y + b4.y, 0.f);
    r.z = fmaxf(a0.z + a1.z + a2.z + a3.z + b4.z, 0.f);
    r.w = fmaxf(a0.w + a1.w + a2.w + a3.w + b4.w, 0.f);
    *(float4*)(out + (size_t)node * 128 + lane * 4) = r;
}

// ---------------- small dense helpers ----------------
__device__ __forceinline__ float dotN(const float* __restrict__ a,
                                      const float* __restrict__ w, int n) {
    float s0 = 0.f, s1 = 0.f, s2 = 0.f, s3 = 0.f;
    for (int k = 0; k < n; k += 4) {
        float4 wv = __ldg((const float4*)(w + k));
        s0 = fmaf(a[k + 0], wv.x, s0);
        s1 = fmaf(a[k + 1], wv.y, s1);
        s2 = fmaf(a[k + 2], wv.z, s2);
        s3 = fmaf(a[k + 3], wv.w, s3);
    }
    return (s0 + s1) + (s2 + s3);
}

__global__ __launch_bounds__(256) void k_mlp(
    const float* __restrict__ mol,
    const float* __restrict__ mW, const float* __restrict__ mB,
    const float* __restrict__ moW, const float* __restrict__ moB)
{
    __shared__ float a[256], b[256];
    int g = blockIdx.x, t = threadIdx.x;
    a[t] = mol[g * 256 + t];
    __syncthreads();
    b[t] = fmaxf(dotN(a, mW + t * 256, 256) + mB[t], 0.f);
    __syncthreads();
    a[t] = fmaxf(dotN(b, mW + 65536 + t * 256, 256) + mB[256 + t], 0.f);
    __syncthreads();
    if (t < 64) d_mlpo[g * 64 + t] = fmaxf(dotN(a, moW + t * 256, 256) + moB[t], 0.f);
}

__global__ __launch_bounds__(256) void k_heads2(
    const float* __restrict__ hnode,
    const float* __restrict__ goW, const float* __restrict__ goB,
    const float* __restrict__ p1W, const float* __restrict__ p1B,
    const float* __restrict__ p2W, const float* __restrict__ p2B,
    const float* __restrict__ oW, const float* __restrict__ oB,
    float* __restrict__ out)
{
    __shared__ float cat[192], pooled[128], red[256], b[256], a[256];
    int g = blockIdx.x, t = threadIdx.x;

    int s = d_gstart[g], e = d_gstart[g + 1];
    float acc = 0.f;
    int f = t & 127, half = t >> 7;
    for (int n = s + half; n < e; n += 2) acc += hnode[(size_t)n * 128 + f];
    red[t] = acc;
    if (t < 64) cat[128 + t] = d_mlpo[g * 64 + t];
    __syncthreads();
    if (t < 128) pooled[t] = (red[t] + red[t + 128]) / (float)max(e - s, 1);
    __syncthreads();
    if (t < 128) cat[t] = (e > s) ? (dotN(pooled, goW + t * 128, 128) + goB[t]) : 0.f;
    __syncthreads();

    b[t] = fmaxf(dotN(cat, p1W + t * 192, 192) + p1B[t], 0.f);
    __syncthreads();
    a[t] = fmaxf(dotN(b, p2W + t * 256, 256) + p2B[t], 0.f);
    __syncthreads();
    red[t] = a[t] * oW[t];
    __syncthreads();
    for (int d = 128; d > 0; d >>= 1) {
        if (t < d) red[t] += red[t + d];
        __syncthreads();
    }
    if (t == 0) out[g] = red[0] + oB[0];
}

// ---------------- host ----------------
struct HxCtx {
    cudaStream_t s1, s2;
    cudaEvent_t ev0, ev1, ev2;
    HxCtx() {
        cudaStreamCreateWithFlags(&s1, cudaStreamNonBlocking);
        cudaStreamCreateWithFlags(&s2, cudaStreamNonBlocking);
        cudaEventCreateWithFlags(&ev0, cudaEventDisableTiming);
        cudaEventCreateWithFlags(&ev1, cudaEventDisableTiming);
        cudaEventCreateWithFlags(&ev2, cudaEventDisableTiming);
    }
};

extern "C" void kernel_launch(void* const* d_in, const int* in_sizes, int n_in,
                              void* d_out, int out_size)
{
    static HxCtx ctx;

    const float* x    = (const float*)d_in[0];
    const void*  ei   = d_in[1];
    const void*  bi   = d_in[2];
    const float* mol  = (const float*)d_in[3];
    const float* gcnW = (const float*)d_in[4];
    const float* gcnB = (const float*)d_in[5];
    const float* goW  = (const float*)d_in[6];
    const float* goB  = (const float*)d_in[7];
    const float* mW   = (const float*)d_in[8];
    const float* mB   = (const float*)d_in[9];
    const float* moW  = (const float*)d_in[10];
    const float* moB  = (const float*)d_in[11];
    const float* p1W  = (const float*)d_in[12];
    const float* p1B  = (const float*)d_in[13];
    const float* p2W  = (const float*)d_in[14];
    const float* p2B  = (const float*)d_in[15];
    const float* oW   = (const float*)d_in[16];
    const float* oB   = (const float*)d_in[17];
    float* out = (float*)d_out;

    void *pA, *pB, *pT;
    cudaGetSymbolAddress(&pA, d_hA);
    cudaGetSymbolAddress(&pB, d_hB);
    cudaGetSymbolAddress(&pT, d_hT);
    float*  hA = (float*)pA;
    float*  hB = (float*)pB;
    __half* hT = (__half*)pT;

    const int nthr = 256;
    int gN = (NN + nthr - 1) / nthr;
    int gE = (NE + nthr - 1) / nthr;
    int gGemm = (NN + 127) / 128;
    int gAgg = (NN * 32 + nthr - 1) / nthr;

    cudaStream_t L = 0;

    k_detect<<<1, 32, 0, L>>>(ei);
    cudaEventRecord(ctx.ev0, L);
    cudaStreamWaitEvent(ctx.s1, ctx.ev0, 0);
    cudaStreamWaitEvent(ctx.s2, ctx.ev0, 0);

    // s1: CSR + norm prep (concurrent with GEMM1)
    k_init<<<gN, nthr, 0, ctx.s1>>>();
    k_hist<<<gE, nthr, 0, ctx.s1>>>(ei);
    k_scan1<<<SCAN_NBLK, SCAN_BLK, 0, ctx.s1>>>();
    k_scan3<<<SCAN_NBLK, SCAN_BLK, 0, ctx.s1>>>();
    k_fill<<<gE, nthr, 0, ctx.s1>>>(ei);
    cudaEventRecord(ctx.ev1, ctx.s1);

    // s2: graph bounds + MLP branch
    k_bounds<<<gN, nthr, 0, ctx.s2>>>(bi);
    k_mlp<<<NG, nthr, 0, ctx.s2>>>(mol, mW, mB, moW, moB);
    cudaEventRecord(ctx.ev2, ctx.s2);

    // legacy: GCN stack
    k_gemm2h<<<gGemm, 256, 0, L>>>(x, gcnW, hT, NN);
    cudaStreamWaitEvent(L, ctx.ev1, 0);
    k_agg<<<gAgg, 256, 0, L>>>(hT, gcnB, hA);
    k_gemm2h<<<gGemm, 256, 0, L>>>(hA, gcnW + 128 * 128, hT, NN);
    k_agg<<<gAgg, 256, 0, L>>>(hT, gcnB + 128, hB);
    k_gemm2h<<<gGemm, 256, 0, L>>>(hB, gcnW + 2 * 128 * 128, hT, NN);
    k_agg<<<gAgg, 256, 0, L>>>(hT, gcnB + 256, hA);

    cudaStreamWaitEvent(L, ctx.ev2, 0);
    k_heads2<<<NG, 256, 0, L>>>(hA, goW, goB, p1W, p1B, p2W, p2B, oW, oB, out);
}

// round 6
// speedup vs baseline: 2.4223x; 1.2666x over previous
#include <cuda_runtime.h>
#include <cuda_fp16.h>

#define NN 50000
#define NE 800000
#define NG 256
#define NF 128
#define SCAN_BLK 1024
#define SCAN_NBLK 49   // 49*1024 = 50176 >= NN+1

typedef unsigned long long u64;

// ---------------- device scratch (no allocation allowed) ----------------
__device__ __half d_hT[NN * NF];     // GEMM out / agg in
__device__ __half d_hX[NN * NF];     // agg out / GEMM in
__device__ __half d_Wh[3 * NF * NF]; // fp16 GCN weights
__device__ float  d_dinv[NN];
__device__ int    d_cnt[NN];
__device__ int    d_off[NN + 1];
__device__ int    d_cursor[NN];
__device__ int2   d_csr[NE];         // {src, w as int bits}
__device__ int    d_partials[64];
__device__ int    d_is64;
__device__ int    d_gstart[NG + 1];
__device__ float  d_mlpo[NG * 64];

__device__ __forceinline__ uint2 pack4h(float4 v) {
    __half2 a = __floats2half2_rn(v.x, v.y);
    __half2 b = __floats2half2_rn(v.z, v.w);
    uint2 r;
    r.x = *(unsigned*)&a;
    r.y = *(unsigned*)&b;
    return r;
}
__device__ __forceinline__ float4 unpack4h(uint2 u) {
    __half2 a = *(__half2*)&u.x;
    __half2 b = *(__half2*)&u.y;
    float2 f0 = __half22float2(a);
    float2 f1 = __half22float2(b);
    return make_float4(f0.x, f0.y, f1.x, f1.y);
}

// ---------------- int32/int64 index handling ----------------
__device__ __forceinline__ int ldidx(const void* p, long long i) {
    if (d_is64) return (int)((const long long*)p)[i];
    return ((const int*)p)[i];
}

// ---------------- prep ----------------
__global__ void k_detect(const void* edge) {
    if (threadIdx.x == 0) {
        const int* p = (const int*)edge;
        int any = 0;
        for (int j = 0; j < 64; j++) any |= p[2 * j + 1];
        d_is64 = (any == 0) ? 1 : 0;
    }
}

__global__ void k_wconv(const float* __restrict__ W) {
    int i = blockIdx.x * blockDim.x + threadIdx.x;
    if (i < 3 * NF * NF) d_Wh[i] = __float2half(W[i]);
}

__global__ void k_init() {
    int i = blockIdx.x * blockDim.x + threadIdx.x;
    if (i < NN) d_cnt[i] = 0;
}

__global__ void k_hist(const void* edge) {
    int e = blockIdx.x * blockDim.x + threadIdx.x;
    if (e >= NE) return;
    int c = ldidx(edge, (long long)NE + e);
    atomicAdd(&d_cnt[c], 1);
}

__global__ void k_scan1() {
    __shared__ int sm[SCAN_BLK];
    int idx = blockIdx.x * SCAN_BLK + threadIdx.x;
    sm[threadIdx.x] = (idx < NN) ? d_cnt[idx] : 0;
    __syncthreads();
    for (int d = SCAN_BLK / 2; d > 0; d >>= 1) {
        if (threadIdx.x < d) sm[threadIdx.x] += sm[threadIdx.x + d];
        __syncthreads();
    }
    if (threadIdx.x == 0) d_partials[blockIdx.x] = sm[0];
}

__global__ void k_scan3() {
    __shared__ int sm[2][SCAN_BLK];
    __shared__ int pb[64];
    int t = threadIdx.x;
    int idx = blockIdx.x * SCAN_BLK + t;
    int v = (idx < NN) ? d_cnt[idx] : 0;
    sm[0][t] = v;
    if (t < 64) pb[t] = (t < (int)blockIdx.x && t < SCAN_NBLK) ? d_partials[t] : 0;
    __syncthreads();
    if (t < 32) pb[t] += pb[t + 32];
    __syncthreads();
    if (t < 16) pb[t] += pb[t + 16];
    __syncthreads();
    if (t < 8) pb[t] += pb[t + 8];
    __syncthreads();
    if (t < 4) { pb[t] += pb[t + 4]; }
    __syncthreads();
    int base = pb[0] + pb[1] + pb[2] + pb[3];
    int cur = 0;
    for (int d = 1; d < SCAN_BLK; d <<= 1) {
        int add = (t >= d) ? sm[cur][t - d] : 0;
        sm[cur ^ 1][t] = sm[cur][t] + add;
        cur ^= 1;
        __syncthreads();
    }
    int excl = base + sm[cur][t] - v;
    if (idx <= NN) d_off[idx] = excl;
    if (idx < NN) {
        d_dinv[idx] = rsqrtf((float)v + 1.0f);
        d_cursor[idx] = excl;
    }
}

__global__ void k_fill(const void* edge) {
    int e = blockIdx.x * blockDim.x + threadIdx.x;
    if (e >= NE) return;
    int r = ldidx(edge, e);
    int c = ldidx(edge, (long long)NE + e);
    int p = atomicAdd(&d_cursor[c], 1);
    d_csr[p] = make_int2(r, __float_as_int(d_dinv[r] * d_dinv[c]));
}

__global__ void k_bounds(const void* batch) {
    int i = blockIdx.x * blockDim.x + threadIdx.x;
    if (i >= NN) return;
    int b = ldidx(batch, i);
    int prev = (i == 0) ? -1 : ldidx(batch, i - 1);
    for (int g = prev + 1; g <= b; g++) d_gstart[g] = i;
    if (i == NN - 1) {
        for (int g = b + 1; g <= NG; g++) d_gstart[g] = NN;
    }
}

// ---------------- node GEMM via HMMA m16n8k16: C[n,j] = sum_k A[n,k]*W[j,k] ----------------
// BM=128, full N=128, full K=128 resident in smem. 256 threads = 8 warps,
// warp tile 32(M) x 64(N). A fp32 (layer 1) or fp16; W fp16; C fp16.
#define SM_STRIDE 136   // halves; row pitch 272B = 16*17 (uint4-aligned, conflict-free frags)

__global__ __launch_bounds__(256) void k_gemmT(
    const void* __restrict__ Ap, int a_fp32,
    const __half* __restrict__ Wh,
    __half* __restrict__ C, int nrows)
{
    extern __shared__ __half smh[];
    __half* Asm = smh;                       // [128][SM_STRIDE]
    __half* Bsm = smh + 128 * SM_STRIDE;     // [128][SM_STRIDE]

    int tid = threadIdx.x;
    int row0 = blockIdx.x * 128;

    // ---- load A tile ----
    if (a_fp32) {
        const float* Af = (const float*)Ap;
#pragma unroll
        for (int i = 0; i < 16; i++) {
            int idx = tid + i * 256;          // float4 index, 4096 total
            int row = idx >> 5;               // 32 float4 per row
            int c4 = (idx & 31) << 2;
            float4 v = make_float4(0.f, 0.f, 0.f, 0.f);
            if (row0 + row < nrows)
                v = *(const float4*)(Af + (size_t)(row0 + row) * 128 + c4);
            *(uint2*)&Asm[row * SM_STRIDE + c4] = pack4h(v);
        }
    } else {
        const uint4* Ah = (const uint4*)Ap;   // 8 halves per uint4, 16 per row
#pragma unroll
        for (int i = 0; i < 8; i++) {
            int idx = tid + i * 256;          // uint4 index, 2048 total
            int row = idx >> 4;
            int c8 = (idx & 15) << 3;
            uint4 v = make_uint4(0u, 0u, 0u, 0u);
            if (row0 + row < nrows)
                v = Ah[(size_t)(row0 + row) * 16 + (idx & 15)];
            *(uint4*)&Asm[row * SM_STRIDE + c8] = v;
        }
    }
    // ---- load W tile (fp16, [j][k] row-major == B col-major) ----
    {
        const uint4* Wv = (const uint4*)Wh;
#pragma unroll
        for (int i = 0; i < 8; i++) {
            int idx = tid + i * 256;
            int row = idx >> 4;
            int c8 = (idx & 15) << 3;
            *(uint4*)&Bsm[row * SM_STRIDE + c8] = Wv[idx];
        }
    }
    __syncthreads();

    int lane = tid & 31, wid = tid >> 5;
    int wm = (wid & 3) * 32;       // warp M offset
    int wn = (wid >> 2) * 64;      // warp N offset
    int r = lane >> 2;
    int c2 = (lane & 3) * 2;

    float acc[2][8][4];
#pragma unroll
    for (int mt = 0; mt < 2; mt++)
#pragma unroll
        for (int nt = 0; nt < 8; nt++)
#pragma unroll
            for (int q = 0; q < 4; q++) acc[mt][nt][q] = 0.f;

#pragma unroll
    for (int ks = 0; ks < 8; ks++) {
        int kb = ks * 16;
        unsigned af[2][4];
#pragma unroll
        for (int mt = 0; mt < 2; mt++) {
            int rowb = wm + mt * 16;
            af[mt][0] = *(unsigned*)&Asm[(rowb + r) * SM_STRIDE + kb + c2];
            af[mt][1] = *(unsigned*)&Asm[(rowb + r + 8) * SM_STRIDE + kb + c2];
            af[mt][2] = *(unsigned*)&Asm[(rowb + r) * SM_STRIDE + kb + c2 + 8];
            af[mt][3] = *(unsigned*)&Asm[(rowb + r + 8) * SM_STRIDE + kb + c2 + 8];
        }
        unsigned bf[8][2];
#pragma unroll
        for (int nt = 0; nt < 8; nt++) {
            int n = wn + nt * 8 + r;
            bf[nt][0] = *(unsigned*)&Bsm[n * SM_STRIDE + kb + c2];
            bf[nt][1] = *(unsigned*)&Bsm[n * SM_STRIDE + kb + c2 + 8];
        }
#pragma unroll
        for (int mt = 0; mt < 2; mt++)
#pragma unroll
            for (int nt = 0; nt < 8; nt++) {
                asm volatile(
                    "mma.sync.aligned.m16n8k16.row.col.f32.f16.f16.f32 "
                    "{%0,%1,%2,%3}, {%4,%5,%6,%7}, {%8,%9}, {%0,%1,%2,%3};"
                    : "+f"(acc[mt][nt][0]), "+f"(acc[mt][nt][1]),
                      "+f"(acc[mt][nt][2]), "+f"(acc[mt][nt][3])
                    : "r"(af[mt][0]), "r"(af[mt][1]), "r"(af[mt][2]), "r"(af[mt][3]),
                      "r"(bf[nt][0]), "r"(bf[nt][1]));
            }
    }

    // ---- epilogue: fp16 stores ----
#pragma unroll
    for (int mt = 0; mt < 2; mt++) {
        int gr0 = row0 + wm + mt * 16 + r;
        int gr1 = gr0 + 8;
#pragma unroll
        for (int nt = 0; nt < 8; nt++) {
            int gc = wn + nt * 8 + c2;
            __half2 h0 = __floats2half2_rn(acc[mt][nt][0], acc[mt][nt][1]);
            __half2 h1 = __floats2half2_rn(acc[mt][nt][2], acc[mt][nt][3]);
            if (gr0 < nrows) *(__half2*)(C + (size_t)gr0 * 128 + gc) = h0;
            if (gr1 < nrows) *(__half2*)(C + (size_t)gr1 * 128 + gc) = h1;
        }
    }
}

// ---------------- GCN aggregation: warp per node, fp16 gather, fp32 accum, fp16 out ----------------
__global__ __launch_bounds__(256) void k_agg(const __half* __restrict__ ht,
                                             const float* __restrict__ bias,
                                             __half* __restrict__ out)
{
    int node = (int)((blockIdx.x * (unsigned)blockDim.x + threadIdx.x) >> 5);
    if (node >= NN) return;
    int lane = threadIdx.x & 31;
    const uint2* base = (const uint2*)ht;

    float di = d_dinv[node];
    float sc = di * di;
    float4 h4 = unpack4h(__ldg(base + (size_t)node * 32 + lane));
    float4 a0 = make_float4(sc * h4.x, sc * h4.y, sc * h4.z, sc * h4.w);
    float4 a1 = make_float4(0.f, 0.f, 0.f, 0.f);
    float4 a2 = a1, a3 = a1;

    int p = d_off[node], e = d_off[node + 1];
    for (; p + 8 <= e; p += 8) {
        int2 cc[8];
        uint2 vv[8];
#pragma unroll
        for (int q = 0; q < 8; q++) cc[q] = __ldg(&d_csr[p + q]);
#pragma unroll
        for (int q = 0; q < 8; q++) vv[q] = __ldg(base + (size_t)cc[q].x * 32 + lane);
#pragma unroll
        for (int q = 0; q < 8; q++) {
            float w = __int_as_float(cc[q].y);
            float4 v = unpack4h(vv[q]);
            float4* a = (q & 3) == 0 ? &a0 : (q & 3) == 1 ? &a1 : (q & 3) == 2 ? &a2 : &a3;
            a->x = fmaf(w, v.x, a->x); a->y = fmaf(w, v.y, a->y);
            a->z = fmaf(w, v.z, a->z); a->w = fmaf(w, v.w, a->w);
        }
    }
    for (; p < e; p++) {
        int2 c = __ldg(&d_csr[p]);
        float4 v = unpack4h(__ldg(base + (size_t)c.x * 32 + lane));
        float w = __int_as_float(c.y);
        a0.x = fmaf(w, v.x, a0.x); a0.y = fmaf(w, v.y, a0.y);
        a0.z = fmaf(w, v.z, a0.z); a0.w = fmaf(w, v.w, a0.w);
    }
    float4 b4 = __ldg((const float4*)bias + lane);
    float4 rv;
    rv.x = fmaxf(a0.x + a1.x + a2.x + a3.x + b4.x, 0.f);
    rv.y = fmaxf(a0.y + a1.y + a2.y + a3.y + b4.y, 0.f);
    rv.z = fmaxf(a0.z + a1.z + a2.z + a3.z + b4.z, 0.f);
    rv.w = fmaxf(a0.w + a1.w + a2.w + a3.w + b4.w, 0.f);
    *(uint2*)(out + (size_t)node * 128 + lane * 4) = pack4h(rv);
}

// ---------------- small dense helpers ----------------
__device__ __forceinline__ float dotN(const float* __restrict__ a,
                                      const float* __restrict__ w, int n) {
    float s0 = 0.f, s1 = 0.f, s2 = 0.f, s3 = 0.f;
    for (int k = 0; k < n; k += 4) {
        float4 wv = __ldg((const float4*)(w + k));
        s0 = fmaf(a[k + 0], wv.x, s0);
        s1 = fmaf(a[k + 1], wv.y, s1);
        s2 = fmaf(a[k + 2], wv.z, s2);
        s3 = fmaf(a[k + 3], wv.w, s3);
    }
    return (s0 + s1) + (s2 + s3);
}

__global__ __launch_bounds__(256) void k_mlp(
    const float* __restrict__ mol,
    const float* __restrict__ mW, const float* __restrict__ mB,
    const float* __restrict__ moW, const float* __restrict__ moB)
{
    __shared__ float a[256], b[256];
    int g = blockIdx.x, t = threadIdx.x;
    a[t] = mol[g * 256 + t];
    __syncthreads();
    b[t] = fmaxf(dotN(a, mW + t * 256, 256) + mB[t], 0.f);
    __syncthreads();
    a[t] = fmaxf(dotN(b, mW + 65536 + t * 256, 256) + mB[256 + t], 0.f);
    __syncthreads();
    if (t < 64) d_mlpo[g * 64 + t] = fmaxf(dotN(a, moW + t * 256, 256) + moB[t], 0.f);
}

__global__ __launch_bounds__(256) void k_heads2(
    const __half* __restrict__ hnode,
    const float* __restrict__ goW, const float* __restrict__ goB,
    const float* __restrict__ p1W, const float* __restrict__ p1B,
    const float* __restrict__ p2W, const float* __restrict__ p2B,
    const float* __restrict__ oW, const float* __restrict__ oB,
    float* __restrict__ out)
{
    __shared__ float cat[192], pooled[128], red[256], b[256], a[256];
    int g = blockIdx.x, t = threadIdx.x;

    int s = d_gstart[g], e = d_gstart[g + 1];
    float acc = 0.f;
    int f = t & 127, half = t >> 7;
    for (int n = s + half; n < e; n += 2)
        acc += __half2float(hnode[(size_t)n * 128 + f]);
    red[t] = acc;
    if (t < 64) cat[128 + t] = d_mlpo[g * 64 + t];
    __syncthreads();
    if (t < 128) pooled[t] = (red[t] + red[t + 128]) / (float)max(e - s, 1);
    __syncthreads();
    if (t < 128) cat[t] = dotN(pooled, goW + t * 128, 128) + goB[t];
    __syncthreads();

    b[t] = fmaxf(dotN(cat, p1W + t * 192, 192) + p1B[t], 0.f);
    __syncthreads();
    a[t] = fmaxf(dotN(b, p2W + t * 256, 256) + p2B[t], 0.f);
    __syncthreads();
    red[t] = a[t] * oW[t];
    __syncthreads();
    for (int d = 128; d > 0; d >>= 1) {
        if (t < d) red[t] += red[t + d];
        __syncthreads();
    }
    if (t == 0) out[g] = red[0] + oB[0];
}

// ---------------- host ----------------
#define GEMM_SMEM (2 * 128 * SM_STRIDE * (int)sizeof(__half))

struct HxCtx {
    cudaStream_t s1, s2;
    cudaEvent_t ev0, ev1, ev2, ev3;
    HxCtx() {
        cudaStreamCreateWithFlags(&s1, cudaStreamNonBlocking);
        cudaStreamCreateWithFlags(&s2, cudaStreamNonBlocking);
        cudaEventCreateWithFlags(&ev0, cudaEventDisableTiming);
        cudaEventCreateWithFlags(&ev1, cudaEventDisableTiming);
        cudaEventCreateWithFlags(&ev2, cudaEventDisableTiming);
        cudaEventCreateWithFlags(&ev3, cudaEventDisableTiming);
        cudaFuncSetAttribute(k_gemmT, cudaFuncAttributeMaxDynamicSharedMemorySize, GEMM_SMEM);
    }
};

extern "C" void kernel_launch(void* const* d_in, const int* in_sizes, int n_in,
                              void* d_out, int out_size)
{
    static HxCtx ctx;

    const float* x    = (const float*)d_in[0];
    const void*  ei   = d_in[1];
    const void*  bi   = d_in[2];
    const float* mol  = (const float*)d_in[3];
    const float* gcnW = (const float*)d_in[4];
    const float* gcnB = (const float*)d_in[5];
    const float* goW  = (const float*)d_in[6];
    const float* goB  = (const float*)d_in[7];
    const float* mW   = (const float*)d_in[8];
    const float* mB   = (const float*)d_in[9];
    const float* moW  = (const float*)d_in[10];
    const float* moB  = (const float*)d_in[11];
    const float* p1W  = (const float*)d_in[12];
    const float* p1B  = (const float*)d_in[13];
    const float* p2W  = (const float*)d_in[14];
    const float* p2B  = (const float*)d_in[15];
    const float* oW   = (const float*)d_in[16];
    const float* oB   = (const float*)d_in[17];
    float* out = (float*)d_out;

    void *pT, *pX, *pW;
    cudaGetSymbolAddress(&pT, d_hT);
    cudaGetSymbolAddress(&pX, d_hX);
    cudaGetSymbolAddress(&pW, d_Wh);
    __half* hT = (__half*)pT;
    __half* hX = (__half*)pX;
    __half* Wh = (__half*)pW;

    const int nthr = 256;
    int gN = (NN + nthr - 1) / nthr;
    int gE = (NE + nthr - 1) / nthr;
    int gGemm = (NN + 127) / 128;
    int gAgg = (NN * 32 + nthr - 1) / nthr;

    cudaStream_t L = 0;

    k_detect<<<1, 32, 0, L>>>(ei);
    cudaEventRecord(ctx.ev0, L);
    cudaStreamWaitEvent(ctx.s1, ctx.ev0, 0);
    cudaStreamWaitEvent(ctx.s2, ctx.ev0, 0);

    // s1: CSR + norm prep (concurrent with GEMM1)
    k_init<<<gN, nthr, 0, ctx.s1>>>();
    k_hist<<<gE, nthr, 0, ctx.s1>>>(ei);
    k_scan1<<<SCAN_NBLK, SCAN_BLK, 0, ctx.s1>>>();
    k_scan3<<<SCAN_NBLK, SCAN_BLK, 0, ctx.s1>>>();
    k_fill<<<gE, nthr, 0, ctx.s1>>>(ei);
    cudaEventRecord(ctx.ev1, ctx.s1);

    // s2: weight convert + graph bounds + MLP branch
    k_wconv<<<(3 * NF * NF + 255) / 256, 256, 0, ctx.s2>>>(gcnW);
    cudaEventRecord(ctx.ev3, ctx.s2);
    k_bounds<<<gN, nthr, 0, ctx.s2>>>(bi);
    k_mlp<<<NG, nthr, 0, ctx.s2>>>(mol, mW, mB, moW, moB);
    cudaEventRecord(ctx.ev2, ctx.s2);

    // legacy: GCN stack (tensor-core GEMMs)
    cudaStreamWaitEvent(L, ctx.ev3, 0);
    k_gemmT<<<gGemm, 256, GEMM_SMEM, L>>>(x, 1, Wh, hT, NN);
    cudaStreamWaitEvent(L, ctx.ev1, 0);
    k_agg<<<gAgg, 256, 0, L>>>(hT, gcnB, hX);
    k_gemmT<<<gGemm, 256, GEMM_SMEM, L>>>(hX, 0, Wh + NF * NF, hT, NN);
    k_agg<<<gAgg, 256, 0, L>>>(hT, gcnB + 128, hX);
    k_gemmT<<<gGemm, 256, GEMM_SMEM, L>>>(hX, 0, Wh + 2 * NF * NF, hT, NN);
    k_agg<<<gAgg, 256, 0, L>>>(hT, gcnB + 256, hX);

    cudaStreamWaitEvent(L, ctx.ev2, 0);
    k_heads2<<<NG, 256, 0, L>>>(hX, goW, goB, p1W, p1B, p2W, p2B, oW, oB, out);
}